// round 3
// baseline (speedup 1.0000x reference)
#include <cuda_runtime.h>
#include <math.h>

#define NB   64
#define G    8
#define NT   512
#define TS   16
#define DIM  128
#define CLIP_LIM 256.0f

#define PSTRIDE 68     // padded sP row stride (floats)
#define RSTRIDE 12     // padded sR row stride (floats): float4-aligned, 3n mod 8 distinct
#define HROWS   16     // h rows per k3 block

__device__ float    g_cdf[NB * NT];           // [n][i][j][k]
__device__ float    g_P[DIM * NB * G * G];    // [d][n][j][k]
__device__ float    g_M[DIM * G];
__device__ unsigned g_minmax[2];

// ---------------------------------------------------------------- helpers
__device__ __forceinline__ float bspline5(float x) {
    float t = fabsf(x);
    float t2 = t * t, t3 = t2 * t, t4 = t2 * t2, t5 = t4 * t;
    if (t < 1.0f)
        return 11.0f/20.0f - 0.5f*t2 + 0.25f*t4 - t5*(1.0f/12.0f);
    if (t < 2.0f)
        return 17.0f/40.0f + t*(5.0f/8.0f) - t2*(7.0f/4.0f) + t3*(5.0f/4.0f)
             - t4*(3.0f/8.0f) + t5*(1.0f/24.0f);
    if (t < 3.0f) {
        float u = 3.0f - t;
        float u2 = u * u;
        return u2 * u2 * u * (1.0f/120.0f);
    }
    return 0.0f;
}

__device__ __forceinline__ int reflect_dct2(int i, int n) {
    int m = i % (2 * n);
    if (m < 0) m += 2 * n;
    return (m < n) ? m : (2 * n - 1 - m);
}

__device__ __forceinline__ unsigned fenc(float f) {
    unsigned u = __float_as_uint(f);
    return (u & 0x80000000u) ? ~u : (u | 0x80000000u);
}
__device__ __forceinline__ float fdec(unsigned e) {
    unsigned u = (e & 0x80000000u) ? (e & 0x7FFFFFFFu) : ~e;
    return __uint_as_float(u);
}

__device__ __forceinline__ float w1poly(float t) {
    return 17.0f/40.0f + t*(5.0f/8.0f + t*(-7.0f/4.0f + t*(5.0f/4.0f
         + t*(-3.0f/8.0f + t*(1.0f/24.0f)))));
}
__device__ __forceinline__ float w0poly(float t) {
    float t2 = t * t;
    float t4 = t2 * t2;
    return 11.0f/20.0f - 0.5f*t2 + 0.25f*t4 - t4*t*(1.0f/12.0f);
}

// ---------------------------------------------------------------- K0
__global__ void k0_matrix() {
    int s = threadIdx.x;
    if (s == 0) { g_minmax[0] = 0xFFFFFFFFu; g_minmax[1] = 0u; }
    if (s < DIM) {
        const float start = -0.53125f;
        const float step  = 8.0625f / 127.0f;
        float c = start + (float)s * step;
        float row[G];
        #pragma unroll
        for (int i = 0; i < G; i++) row[i] = 0.0f;
        int base = (int)floorf(c) - 2;
        #pragma unroll
        for (int t = 0; t < 6; t++) {
            int tap = base + t;
            float w = bspline5(c - (float)tap);
            row[reflect_dct2(tap, G)] += w;
        }
        #pragma unroll
        for (int i = 0; i < G; i++) g_M[s * G + i] = row[i];
    }
}

// ---------------------------------------------------------------- K1
__global__ void __launch_bounds__(256) k1_hist(const float* __restrict__ x) {
    __shared__ float hist8[8][NB];
    int tile = blockIdx.x;
    int ti = tile >> 6, tj = (tile >> 3) & 7, tk = tile & 7;
    int tid = threadIdx.x;
    int warp = tid >> 5;

    for (int i = tid; i < 8 * NB; i += 256) ((float*)hist8)[i] = 0.0f;
    __syncthreads();

    int b  = tid >> 4;
    int cc = tid & 15;
    int d0 = ti * TS, h0 = tj * TS, w0 = tk * TS;
    for (int a = 0; a < TS; a++) {
        float v = x[((d0 + a) * DIM + (h0 + b)) * DIM + (w0 + cc)];
        float pos = v * 63.0f;
        int nb = __float2int_rn(pos);
        nb = min(63, max(0, nb));
        float u = (pos - (float)nb) * (1000.0f / 63.0f);
        atomicAdd(&hist8[warp][nb], __expf(-0.5f * u * u));
    }
    __syncthreads();

    if (tid < NB) {
        float s = 0.0f;
        #pragma unroll
        for (int w = 0; w < 8; w++) s += hist8[w][tid];
        hist8[0][tid] = s;
    }
    __syncthreads();

    if (tid == 0) {
        float s = 0.0f;
        float pdf[NB];
        for (int n = 0; n < NB; n++) { pdf[n] = hist8[0][n] * (1.0f / 4096.0f); s += pdf[n]; }
        float inv = 1.0f / (s + 1e-10f);
        float tot = 0.0f;
        float h2[NB];
        for (int n = 0; n < NB; n++) {
            float hh = fminf(pdf[n] * inv * 4096.0f, CLIP_LIM);
            h2[n] = hh;
            tot += hh;
        }
        float clipped  = 4096.0f - tot;
        float residual = fmodf(clipped, 64.0f);
        float redist   = (clipped - residual) * (1.0f / 64.0f);
        float c = 0.0f;
        int tbase = ti * 64 + tj * 8 + tk;
        for (int n = 0; n < NB; n++) {
            float hv = h2[n] + redist + (((float)n < residual) ? 1.0f : 0.0f);
            c += hv;
            g_cdf[n * NT + tbase] = c * (63.0f / 4096.0f);
        }
    }
}

// ---------------------------------------------------------------- K2
__global__ void k2_P() {
    int idx = blockIdx.x * blockDim.x + threadIdx.x;
    int k = idx & 7;
    int j = (idx >> 3) & 7;
    int n = (idx >> 6) & 63;
    int d = idx >> 12;
    float acc = 0.0f;
    #pragma unroll
    for (int i = 0; i < 8; i++)
        acc += g_M[d * 8 + i] * g_cdf[n * NT + i * 64 + j * 8 + k];
    g_P[idx] = acc;
}

// ---------------------------------------------------------------- K3
// grid (8, 128): y = d slice, x = h sixteenth (16 rows). 256 thr = 2 h-rows x 128 w.
__global__ void __launch_bounds__(256) k3_final(const float* __restrict__ x,
                                                float* __restrict__ out) {
    __shared__ __align__(16) float sP[NB * PSTRIDE];       // 17408 B
    __shared__ __align__(16) float sMh[HROWS * G];         // 512 B
    __shared__ __align__(16) float sR[2][2][NB * RSTRIDE]; // 12 KB

    int d   = blockIdx.y;
    int hb  = blockIdx.x * HROWS;
    int tid = threadIdx.x;
    int hsub = tid >> 7;
    int w    = tid & 127;

    for (int i = tid; i < NB * G * G; i += 256) {
        int n = i >> 6, r = i & 63;
        sP[n * PSTRIDE + r] = g_P[d * NB * G * G + i];
    }
    if (tid < HROWS * G) sMh[tid] = g_M[hb * G + tid];

    float4 mwlo, mwhi;
    {
        const float* m = &g_M[w * G];
        mwlo = make_float4(m[0], m[1], m[2], m[3]);
        mwhi = make_float4(m[4], m[5], m[6], m[7]);
    }
    __syncthreads();

    int lane128 = tid & 127;
    int bn = lane128 & 63;
    int bk = (lane128 >> 6) << 2;

    auto build = [&](int it, int buf) {
        int hl = 2 * it + hsub;
        float4 acc = make_float4(0.f, 0.f, 0.f, 0.f);
        #pragma unroll
        for (int j = 0; j < 8; j++) {
            float m = sMh[hl * 8 + j];
            float4 p = *(const float4*)&sP[bn * PSTRIDE + j * 8 + bk];
            acc.x += m * p.x; acc.y += m * p.y; acc.z += m * p.z; acc.w += m * p.w;
        }
        *(float4*)&sR[buf][hsub][bn * RSTRIDE + bk] = acc;
    };

    build(0, 0);

    // prefetch voxel for iteration 0
    float vcur = x[(d * DIM + (hb + hsub)) * DIM + w];
    __syncthreads();

    float vmin =  3.0e38f, vmax = -3.0e38f;

    #pragma unroll 2
    for (int it = 0; it < HROWS / 2; it++) {
        int buf = it & 1;
        // prefetch next voxel (global latency overlaps build + this iter's math)
        float vnext = 0.0f;
        if (it + 1 < HROWS / 2) {
            int hn = hb + 2 * (it + 1) + hsub;
            vnext = x[(d * DIM + hn) * DIM + w];
            build(it + 1, buf ^ 1);
        }

        int h = hb + 2 * it + hsub;
        float cb = vcur * 63.0f;
        float fb = floorf(cb);
        int base = (int)fb - 2;
        float f  = cb - fb;
        float g1 = 1.0f - f;

        float f5g = f * f; f5g = f5g * f5g * f;
        float g5g = g1 * g1; g5g = g5g * g5g * g1;
        float wb[6];
        wb[0] = g5g * (1.0f / 120.0f);
        wb[1] = w1poly(1.0f + f);
        wb[2] = w0poly(f);
        wb[3] = w0poly(g1);
        wb[4] = w1poly(2.0f - f);
        wb[5] = f5g * (1.0f / 120.0f);

        const float* R = sR[buf][hsub];
        float acc = 0.0f;
        #pragma unroll
        for (int t = 0; t < 6; t++) {
            int tap = base + t;
            int n = (tap < 0) ? (-1 - tap) : ((tap > 63) ? (127 - tap) : tap);
            const float4* r4 = (const float4*)(R + n * RSTRIDE);
            float4 a = r4[0], b4 = r4[1];
            float s = mwlo.x * a.x + mwlo.y * a.y + mwlo.z * a.z + mwlo.w * a.w
                    + mwhi.x * b4.x + mwhi.y * b4.y + mwhi.z * b4.z + mwhi.w * b4.w;
            acc = fmaf(wb[t], s, acc);
        }
        out[(d * DIM + h) * DIM + w] = acc;
        vmin = fminf(vmin, acc);
        vmax = fmaxf(vmax, acc);
        vcur = vnext;
        __syncthreads();
    }

    #pragma unroll
    for (int off = 16; off > 0; off >>= 1) {
        vmin = fminf(vmin, __shfl_xor_sync(0xFFFFFFFFu, vmin, off));
        vmax = fmaxf(vmax, __shfl_xor_sync(0xFFFFFFFFu, vmax, off));
    }
    if ((tid & 31) == 0) {
        atomicMin(&g_minmax[0], fenc(vmin));
        atomicMax(&g_minmax[1], fenc(vmax));
    }
}

// ---------------------------------------------------------------- K4
__global__ void k4_norm(float4* __restrict__ out, int n4) {
    int i = blockIdx.x * blockDim.x + threadIdx.x;
    float mn = fdec(g_minmax[0]);
    float mx = fdec(g_minmax[1]);
    float inv = 1.0f / (mx - mn + 1e-10f);
    if (i < n4) {
        float4 v = out[i];
        v.x = (v.x - mn) * inv;
        v.y = (v.y - mn) * inv;
        v.z = (v.z - mn) * inv;
        v.w = (v.w - mn) * inv;
        out[i] = v;
    }
}

// ---------------------------------------------------------------- launch
extern "C" void kernel_launch(void* const* d_in, const int* in_sizes, int n_in,
                              void* d_out, int out_size) {
    const float* x = (const float*)d_in[0];
    float* out = (float*)d_out;

    k0_matrix<<<1, 128>>>();
    k1_hist<<<NT, 256>>>(x);
    k2_P<<<(DIM * NB * G * G) / 256, 256>>>();
    k3_final<<<dim3(DIM / HROWS, DIM), 256>>>(x, out);
    int n4 = out_size / 4;
    k4_norm<<<(n4 + 255) / 256, 256>>>((float4*)out, n4);
}

// round 4
// speedup vs baseline: 1.0853x; 1.0853x over previous
#include <cuda_runtime.h>
#include <math.h>

#define NB   64
#define G    8
#define NT   512
#define TS   16
#define DIM  128
#define CLIP_LIM 256.0f

#define PSTRIDE 68     // padded stage row stride (floats)
#define RSTRIDE 12     // padded sR row stride (floats): quad class 3n mod 8 bijective
#define HROWS   16     // h rows per k3 block

__device__ float    g_cdf[NB * NT];           // [n][i][j][k]
__device__ float    g_P[DIM * NB * G * G];    // [d][n][j][k]
__device__ float    g_M[DIM * G];
__device__ unsigned g_minmax[2];

// ---------------------------------------------------------------- helpers
__device__ __forceinline__ float bspline5(float x) {
    float t = fabsf(x);
    float t2 = t * t, t3 = t2 * t, t4 = t2 * t2, t5 = t4 * t;
    if (t < 1.0f)
        return 11.0f/20.0f - 0.5f*t2 + 0.25f*t4 - t5*(1.0f/12.0f);
    if (t < 2.0f)
        return 17.0f/40.0f + t*(5.0f/8.0f) - t2*(7.0f/4.0f) + t3*(5.0f/4.0f)
             - t4*(3.0f/8.0f) + t5*(1.0f/24.0f);
    if (t < 3.0f) {
        float u = 3.0f - t;
        float u2 = u * u;
        return u2 * u2 * u * (1.0f/120.0f);
    }
    return 0.0f;
}

__device__ __forceinline__ int reflect_dct2(int i, int n) {
    int m = i % (2 * n);
    if (m < 0) m += 2 * n;
    return (m < n) ? m : (2 * n - 1 - m);
}

__device__ __forceinline__ unsigned fenc(float f) {
    unsigned u = __float_as_uint(f);
    return (u & 0x80000000u) ? ~u : (u | 0x80000000u);
}
__device__ __forceinline__ float fdec(unsigned e) {
    unsigned u = (e & 0x80000000u) ? (e & 0x7FFFFFFFu) : ~e;
    return __uint_as_float(u);
}

__device__ __forceinline__ float w1poly(float t) {
    return 17.0f/40.0f + t*(5.0f/8.0f + t*(-7.0f/4.0f + t*(5.0f/4.0f
         + t*(-3.0f/8.0f + t*(1.0f/24.0f)))));
}
__device__ __forceinline__ float w0poly(float t) {
    float t2 = t * t;
    float t4 = t2 * t2;
    return 11.0f/20.0f - 0.5f*t2 + 0.25f*t4 - t4*t*(1.0f/12.0f);
}

// ---------------------------------------------------------------- K0
__global__ void k0_matrix() {
    int s = threadIdx.x;
    if (s == 0) { g_minmax[0] = 0xFFFFFFFFu; g_minmax[1] = 0u; }
    if (s < DIM) {
        const float start = -0.53125f;
        const float step  = 8.0625f / 127.0f;
        float c = start + (float)s * step;
        float row[G];
        #pragma unroll
        for (int i = 0; i < G; i++) row[i] = 0.0f;
        int base = (int)floorf(c) - 2;
        #pragma unroll
        for (int t = 0; t < 6; t++) {
            int tap = base + t;
            float w = bspline5(c - (float)tap);
            row[reflect_dct2(tap, G)] += w;
        }
        #pragma unroll
        for (int i = 0; i < G; i++) g_M[s * G + i] = row[i];
    }
}

// ---------------------------------------------------------------- K1
__global__ void __launch_bounds__(256) k1_hist(const float* __restrict__ x) {
    __shared__ float hist8[8][NB];
    int tile = blockIdx.x;
    int ti = tile >> 6, tj = (tile >> 3) & 7, tk = tile & 7;
    int tid = threadIdx.x;
    int warp = tid >> 5;

    for (int i = tid; i < 8 * NB; i += 256) ((float*)hist8)[i] = 0.0f;
    __syncthreads();

    int b  = tid >> 4;
    int cc = tid & 15;
    int d0 = ti * TS, h0 = tj * TS, w0 = tk * TS;
    for (int a = 0; a < TS; a++) {
        float v = x[((d0 + a) * DIM + (h0 + b)) * DIM + (w0 + cc)];
        float pos = v * 63.0f;
        int nb = __float2int_rn(pos);
        nb = min(63, max(0, nb));
        float u = (pos - (float)nb) * (1000.0f / 63.0f);
        atomicAdd(&hist8[warp][nb], __expf(-0.5f * u * u));
    }
    __syncthreads();

    if (tid < NB) {
        float s = 0.0f;
        #pragma unroll
        for (int w = 0; w < 8; w++) s += hist8[w][tid];
        hist8[0][tid] = s;
    }
    __syncthreads();

    if (tid == 0) {
        float s = 0.0f;
        float pdf[NB];
        for (int n = 0; n < NB; n++) { pdf[n] = hist8[0][n] * (1.0f / 4096.0f); s += pdf[n]; }
        float inv = 1.0f / (s + 1e-10f);
        float tot = 0.0f;
        float h2[NB];
        for (int n = 0; n < NB; n++) {
            float hh = fminf(pdf[n] * inv * 4096.0f, CLIP_LIM);
            h2[n] = hh;
            tot += hh;
        }
        float clipped  = 4096.0f - tot;
        float residual = fmodf(clipped, 64.0f);
        float redist   = (clipped - residual) * (1.0f / 64.0f);
        float c = 0.0f;
        int tbase = ti * 64 + tj * 8 + tk;
        for (int n = 0; n < NB; n++) {
            float hv = h2[n] + redist + (((float)n < residual) ? 1.0f : 0.0f);
            c += hv;
            g_cdf[n * NT + tbase] = c * (63.0f / 4096.0f);
        }
    }
}

// ---------------------------------------------------------------- K2
__global__ void k2_P() {
    int idx = blockIdx.x * blockDim.x + threadIdx.x;
    int k = idx & 7;
    int j = (idx >> 3) & 7;
    int n = (idx >> 6) & 63;
    int d = idx >> 12;
    float acc = 0.0f;
    #pragma unroll
    for (int i = 0; i < 8; i++)
        acc += g_M[d * 8 + i] * g_cdf[n * NT + i * 64 + j * 8 + k];
    g_P[idx] = acc;
}

// ---------------------------------------------------------------- K3
// grid (8, 128): y = d slice, x = 16 h-rows. 256 thr = 2 h-rows x 128 w per iter.
// P slice cached in REGISTERS per thread (8 float2); build stage does zero LDS reads.
__global__ void __launch_bounds__(256, 4) k3_final(const float* __restrict__ x,
                                                   float* __restrict__ out) {
    // union: stage (64*68 floats = 17408 B) overlaps sR (2*2*768 floats = 12288 B)
    __shared__ __align__(16) float raw[NB * PSTRIDE];
    __shared__ __align__(16) float sMh[HROWS * G];   // 512 B

    float* stage = raw;
    float* sRb   = raw;   // sR[buf][hsub][n*RSTRIDE + k] = raw[((buf*2+hsub)*NB*RSTRIDE) + ...]

    int d   = blockIdx.y;
    int hb  = blockIdx.x * HROWS;
    int tid = threadIdx.x;
    int hsub = tid >> 7;
    int w    = tid & 127;

    // stage P coalesced into padded smem
    for (int i = tid; i < NB * G * G; i += 256) {
        int n = i >> 6, r = i & 63;
        stage[n * PSTRIDE + r] = g_P[d * NB * G * G + i];
    }
    if (tid < HROWS * G) sMh[tid] = g_M[hb * G + tid];

    float4 mwlo, mwhi;
    {
        const float* m = &g_M[w * G];
        mwlo = make_float4(m[0], m[1], m[2], m[3]);
        mwhi = make_float4(m[4], m[5], m[6], m[7]);
    }
    __syncthreads();

    // pull this thread's P slice into registers: P[bn][j][bq*2 .. bq*2+1]
    int bn = tid & 63;
    int bq = tid >> 6;          // 0..3
    float2 p[8];
    #pragma unroll
    for (int j = 0; j < 8; j++)
        p[j] = *(const float2*)&stage[bn * PSTRIDE + j * 8 + bq * 2];
    __syncthreads();            // stage region now dead -> reused as sR

    int rout = bn * RSTRIDE + bq * 2;

    // build both h-rows of iteration it into buffer buf: pure register FMA
    auto build = [&](int it, int buf) {
        float2 a0 = make_float2(0.f, 0.f), a1 = make_float2(0.f, 0.f);
        #pragma unroll
        for (int j = 0; j < 8; j++) {
            float m0 = sMh[(2 * it)     * 8 + j];
            float m1 = sMh[(2 * it + 1) * 8 + j];
            a0.x = fmaf(m0, p[j].x, a0.x);  a0.y = fmaf(m0, p[j].y, a0.y);
            a1.x = fmaf(m1, p[j].x, a1.x);  a1.y = fmaf(m1, p[j].y, a1.y);
        }
        *(float2*)&sRb[(buf * 2 + 0) * NB * RSTRIDE + rout] = a0;
        *(float2*)&sRb[(buf * 2 + 1) * NB * RSTRIDE + rout] = a1;
    };

    build(0, 0);
    float vcur = x[(d * DIM + (hb + hsub)) * DIM + w];
    __syncthreads();

    float vmin =  3.0e38f, vmax = -3.0e38f;

    #pragma unroll 2
    for (int it = 0; it < HROWS / 2; it++) {
        int buf = it & 1;
        float vnext = 0.0f;
        if (it + 1 < HROWS / 2) {
            int hn = hb + 2 * (it + 1) + hsub;
            vnext = x[(d * DIM + hn) * DIM + w];
            build(it + 1, buf ^ 1);
        }

        int h = hb + 2 * it + hsub;
        float cb = vcur * 63.0f;
        float fb = floorf(cb);
        int base = (int)fb - 2;
        float f  = cb - fb;
        float g1 = 1.0f - f;

        float f5g = f * f; f5g = f5g * f5g * f;
        float g5g = g1 * g1; g5g = g5g * g5g * g1;
        float wb[6];
        wb[0] = g5g * (1.0f / 120.0f);
        wb[1] = w1poly(1.0f + f);
        wb[2] = w0poly(f);
        wb[3] = w0poly(g1);
        wb[4] = w1poly(2.0f - f);
        wb[5] = f5g * (1.0f / 120.0f);

        const float* R = &sRb[(buf * 2 + hsub) * NB * RSTRIDE];
        float acc = 0.0f;
        #pragma unroll
        for (int t = 0; t < 6; t++) {
            int tap = base + t;
            int n = (tap < 0) ? (-1 - tap) : ((tap > 63) ? (127 - tap) : tap);
            const float4* r4 = (const float4*)(R + n * RSTRIDE);
            float4 a = r4[0], b4 = r4[1];
            float s = mwlo.x * a.x + mwlo.y * a.y + mwlo.z * a.z + mwlo.w * a.w
                    + mwhi.x * b4.x + mwhi.y * b4.y + mwhi.z * b4.z + mwhi.w * b4.w;
            acc = fmaf(wb[t], s, acc);
        }
        out[(d * DIM + h) * DIM + w] = acc;
        vmin = fminf(vmin, acc);
        vmax = fmaxf(vmax, acc);
        vcur = vnext;
        __syncthreads();
    }

    #pragma unroll
    for (int off = 16; off > 0; off >>= 1) {
        vmin = fminf(vmin, __shfl_xor_sync(0xFFFFFFFFu, vmin, off));
        vmax = fmaxf(vmax, __shfl_xor_sync(0xFFFFFFFFu, vmax, off));
    }
    if ((tid & 31) == 0) {
        atomicMin(&g_minmax[0], fenc(vmin));
        atomicMax(&g_minmax[1], fenc(vmax));
    }
}

// ---------------------------------------------------------------- K4
__global__ void k4_norm(float4* __restrict__ out, int n4) {
    int i = blockIdx.x * blockDim.x + threadIdx.x;
    float mn = fdec(g_minmax[0]);
    float mx = fdec(g_minmax[1]);
    float inv = 1.0f / (mx - mn + 1e-10f);
    if (i < n4) {
        float4 v = out[i];
        v.x = (v.x - mn) * inv;
        v.y = (v.y - mn) * inv;
        v.z = (v.z - mn) * inv;
        v.w = (v.w - mn) * inv;
        out[i] = v;
    }
}

// ---------------------------------------------------------------- launch
extern "C" void kernel_launch(void* const* d_in, const int* in_sizes, int n_in,
                              void* d_out, int out_size) {
    const float* x = (const float*)d_in[0];
    float* out = (float*)d_out;

    k0_matrix<<<1, 128>>>();
    k1_hist<<<NT, 256>>>(x);
    k2_P<<<(DIM * NB * G * G) / 256, 256>>>();
    k3_final<<<dim3(DIM / HROWS, DIM), 256>>>(x, out);
    int n4 = out_size / 4;
    k4_norm<<<(n4 + 255) / 256, 256>>>((float4*)out, n4);
}

// round 5
// speedup vs baseline: 1.1870x; 1.0938x over previous
#include <cuda_runtime.h>
#include <math.h>

#define NB   64
#define G    8
#define NT   512
#define TS   16
#define DIM  128
#define CLIP_LIM 256.0f

#define RSTRIDE 12     // padded sR row stride (floats): quad class 3n mod 8 bijective
#define HROWS   8      // h rows per k3 block

__device__ float    g_cdf[NB * NT];           // [n][i][j][k]
__device__ float    g_P[DIM * NB * G * G];    // [d][n][j][k]
__device__ float    g_M[DIM * G];
__device__ unsigned g_minmax[2];

// ---------------------------------------------------------------- helpers
__device__ __forceinline__ float bspline5(float x) {
    float t = fabsf(x);
    float t2 = t * t, t3 = t2 * t, t4 = t2 * t2, t5 = t4 * t;
    if (t < 1.0f)
        return 11.0f/20.0f - 0.5f*t2 + 0.25f*t4 - t5*(1.0f/12.0f);
    if (t < 2.0f)
        return 17.0f/40.0f + t*(5.0f/8.0f) - t2*(7.0f/4.0f) + t3*(5.0f/4.0f)
             - t4*(3.0f/8.0f) + t5*(1.0f/24.0f);
    if (t < 3.0f) {
        float u = 3.0f - t;
        float u2 = u * u;
        return u2 * u2 * u * (1.0f/120.0f);
    }
    return 0.0f;
}

__device__ __forceinline__ int reflect_dct2(int i, int n) {
    int m = i % (2 * n);
    if (m < 0) m += 2 * n;
    return (m < n) ? m : (2 * n - 1 - m);
}

__device__ __forceinline__ unsigned fenc(float f) {
    unsigned u = __float_as_uint(f);
    return (u & 0x80000000u) ? ~u : (u | 0x80000000u);
}
__device__ __forceinline__ float fdec(unsigned e) {
    unsigned u = (e & 0x80000000u) ? (e & 0x7FFFFFFFu) : ~e;
    return __uint_as_float(u);
}

__device__ __forceinline__ float w1poly(float t) {
    return 17.0f/40.0f + t*(5.0f/8.0f + t*(-7.0f/4.0f + t*(5.0f/4.0f
         + t*(-3.0f/8.0f + t*(1.0f/24.0f)))));
}
__device__ __forceinline__ float w0poly(float t) {
    float t2 = t * t;
    float t4 = t2 * t2;
    return 11.0f/20.0f - 0.5f*t2 + 0.25f*t4 - t4*t*(1.0f/12.0f);
}

// ---------------------------------------------------------------- K0
__global__ void k0_matrix() {
    int s = threadIdx.x;
    if (s == 0) { g_minmax[0] = 0xFFFFFFFFu; g_minmax[1] = 0u; }
    if (s < DIM) {
        const float start = -0.53125f;
        const float step  = 8.0625f / 127.0f;
        float c = start + (float)s * step;
        float row[G];
        #pragma unroll
        for (int i = 0; i < G; i++) row[i] = 0.0f;
        int base = (int)floorf(c) - 2;
        #pragma unroll
        for (int t = 0; t < 6; t++) {
            int tap = base + t;
            float w = bspline5(c - (float)tap);
            row[reflect_dct2(tap, G)] += w;
        }
        #pragma unroll
        for (int i = 0; i < G; i++) g_M[s * G + i] = row[i];
    }
}

// ---------------------------------------------------------------- K1: float4 loads, nearest-bin KDE
__global__ void __launch_bounds__(256) k1_hist(const float* __restrict__ x) {
    __shared__ float hist8[8][NB];
    int tile = blockIdx.x;
    int ti = tile >> 6, tj = (tile >> 3) & 7, tk = tile & 7;
    int tid = threadIdx.x;
    int warp = tid >> 5;

    for (int i = tid; i < 8 * NB; i += 256) ((float*)hist8)[i] = 0.0f;
    __syncthreads();

    int d0 = ti * TS, h0 = tj * TS, w0 = tk * TS;
    const float4* x4 = (const float4*)x;

    #pragma unroll
    for (int it = 0; it < 4; it++) {
        int f  = it * 256 + tid;      // 0..1023 float4 index within tile
        int w4 = f & 3;
        int rc = f >> 2;              // 0..255
        int a  = rc >> 4, b = rc & 15;
        float4 v = x4[((((d0 + a) * DIM) + (h0 + b)) * DIM + w0) / 4 + w4];

        float vv[4] = {v.x, v.y, v.z, v.w};
        #pragma unroll
        for (int q = 0; q < 4; q++) {
            float pos = vv[q] * 63.0f;
            int nb = __float2int_rn(pos);
            nb = min(63, max(0, nb));
            float u = (pos - (float)nb) * (1000.0f / 63.0f);
            atomicAdd(&hist8[warp][nb], __expf(-0.5f * u * u));
        }
    }
    __syncthreads();

    if (tid < NB) {
        float s = 0.0f;
        #pragma unroll
        for (int w = 0; w < 8; w++) s += hist8[w][tid];
        hist8[0][tid] = s;
    }
    __syncthreads();

    if (tid == 0) {
        float s = 0.0f;
        float pdf[NB];
        for (int n = 0; n < NB; n++) { pdf[n] = hist8[0][n] * (1.0f / 4096.0f); s += pdf[n]; }
        float inv = 1.0f / (s + 1e-10f);
        float tot = 0.0f;
        float h2[NB];
        for (int n = 0; n < NB; n++) {
            float hh = fminf(pdf[n] * inv * 4096.0f, CLIP_LIM);
            h2[n] = hh;
            tot += hh;
        }
        float clipped  = 4096.0f - tot;
        float residual = fmodf(clipped, 64.0f);
        float redist   = (clipped - residual) * (1.0f / 64.0f);
        float c = 0.0f;
        int tbase = ti * 64 + tj * 8 + tk;
        for (int n = 0; n < NB; n++) {
            float hv = h2[n] + redist + (((float)n < residual) ? 1.0f : 0.0f);
            c += hv;
            g_cdf[n * NT + tbase] = c * (63.0f / 4096.0f);
        }
    }
}

// ---------------------------------------------------------------- K2
__global__ void k2_P() {
    int idx = blockIdx.x * blockDim.x + threadIdx.x;
    int k = idx & 7;
    int j = (idx >> 3) & 7;
    int n = (idx >> 6) & 63;
    int d = idx >> 12;
    float acc = 0.0f;
    #pragma unroll
    for (int i = 0; i < 8; i++)
        acc += g_M[d * 8 + i] * g_cdf[n * NT + i * 64 + j * 8 + k];
    g_P[idx] = acc;
}

// ---------------------------------------------------------------- K3
// grid (16, 128): y = d slice, x = 8 h-rows. All 8 R rows built upfront,
// then a completely sync-free voxel loop (4 voxels/thread, fully unrolled).
__global__ void __launch_bounds__(256, 5) k3_final(const float* __restrict__ x,
                                                   float* __restrict__ out) {
    __shared__ __align__(16) float sR[HROWS * NB * RSTRIDE];  // 24576 B
    __shared__ float sMh[HROWS * G];                          // 256 B

    int d   = blockIdx.y;
    int hb  = blockIdx.x * HROWS;
    int tid = threadIdx.x;
    int hsub = tid >> 7;
    int w    = tid & 127;

    // prefetch this thread's 4 voxels (rows hsub, 2+hsub, 4+hsub, 6+hsub)
    float xv[4];
    #pragma unroll
    for (int i = 0; i < 4; i++)
        xv[i] = x[(d * DIM + hb + 2 * i + hsub) * DIM + w];

    if (tid < HROWS * G) sMh[tid] = g_M[hb * G + tid];

    // p slice direct global->regs: P[d][bn][j][bq*2 .. bq*2+1]
    int bn = tid >> 2;          // 0..63
    int bq = tid & 3;           // 0..3
    float2 p[8];
    #pragma unroll
    for (int j = 0; j < 8; j++)
        p[j] = *(const float2*)&g_P[((d * NB + bn) * G + j) * G + bq * 2];

    // per-thread w weights
    float4 mwlo, mwhi;
    {
        const float* m = &g_M[w * G];
        mwlo = make_float4(m[0], m[1], m[2], m[3]);
        mwhi = make_float4(m[4], m[5], m[6], m[7]);
    }
    __syncthreads();   // sMh ready

    // build all 8 R rows: pure register FMA, conflict-light stores
    int rout = bn * RSTRIDE + bq * 2;
    #pragma unroll
    for (int r = 0; r < HROWS; r++) {
        float2 a = make_float2(0.f, 0.f);
        #pragma unroll
        for (int j = 0; j < 8; j++) {
            float m = sMh[r * 8 + j];
            a.x = fmaf(m, p[j].x, a.x);
            a.y = fmaf(m, p[j].y, a.y);
        }
        *(float2*)&sR[r * NB * RSTRIDE + rout] = a;
    }
    __syncthreads();   // the ONLY barrier before the voxel loop

    float vmin =  3.0e38f, vmax = -3.0e38f;

    #pragma unroll
    for (int i = 0; i < 4; i++) {
        int r = 2 * i + hsub;
        float v  = xv[i];
        float cb = v * 63.0f;
        float fb = floorf(cb);
        int base = (int)fb - 2;
        float f  = cb - fb;
        float g1 = 1.0f - f;

        float f5g = f * f; f5g = f5g * f5g * f;
        float g5g = g1 * g1; g5g = g5g * g5g * g1;
        float wb[6];
        wb[0] = g5g * (1.0f / 120.0f);
        wb[1] = w1poly(1.0f + f);
        wb[2] = w0poly(f);
        wb[3] = w0poly(g1);
        wb[4] = w1poly(2.0f - f);
        wb[5] = f5g * (1.0f / 120.0f);

        const float* R = &sR[r * NB * RSTRIDE];
        float acc = 0.0f;
        #pragma unroll
        for (int t = 0; t < 6; t++) {
            int tap = base + t;
            int n = (tap < 0) ? (-1 - tap) : ((tap > 63) ? (127 - tap) : tap);
            const float4* r4 = (const float4*)(R + n * RSTRIDE);
            float4 a = r4[0], b4 = r4[1];
            float s = mwlo.x * a.x + mwlo.y * a.y + mwlo.z * a.z + mwlo.w * a.w
                    + mwhi.x * b4.x + mwhi.y * b4.y + mwhi.z * b4.z + mwhi.w * b4.w;
            acc = fmaf(wb[t], s, acc);
        }
        out[(d * DIM + hb + r) * DIM + w] = acc;
        vmin = fminf(vmin, acc);
        vmax = fmaxf(vmax, acc);
    }

    #pragma unroll
    for (int off = 16; off > 0; off >>= 1) {
        vmin = fminf(vmin, __shfl_xor_sync(0xFFFFFFFFu, vmin, off));
        vmax = fmaxf(vmax, __shfl_xor_sync(0xFFFFFFFFu, vmax, off));
    }
    if ((tid & 31) == 0) {
        atomicMin(&g_minmax[0], fenc(vmin));
        atomicMax(&g_minmax[1], fenc(vmax));
    }
}

// ---------------------------------------------------------------- K4
__global__ void k4_norm(float4* __restrict__ out, int n4) {
    int i = blockIdx.x * blockDim.x + threadIdx.x;
    float mn = fdec(g_minmax[0]);
    float mx = fdec(g_minmax[1]);
    float inv = 1.0f / (mx - mn + 1e-10f);
    if (i < n4) {
        float4 v = out[i];
        v.x = (v.x - mn) * inv;
        v.y = (v.y - mn) * inv;
        v.z = (v.z - mn) * inv;
        v.w = (v.w - mn) * inv;
        out[i] = v;
    }
}

// ---------------------------------------------------------------- launch
extern "C" void kernel_launch(void* const* d_in, const int* in_sizes, int n_in,
                              void* d_out, int out_size) {
    const float* x = (const float*)d_in[0];
    float* out = (float*)d_out;

    k0_matrix<<<1, 128>>>();
    k1_hist<<<NT, 256>>>(x);
    k2_P<<<(DIM * NB * G * G) / 256, 256>>>();
    k3_final<<<dim3(DIM / HROWS, DIM), 256>>>(x, out);
    int n4 = out_size / 4;
    k4_norm<<<(n4 + 255) / 256, 256>>>((float4*)out, n4);
}

// round 6
// speedup vs baseline: 1.4076x; 1.1859x over previous
#include <cuda_runtime.h>
#include <cuda_fp16.h>
#include <math.h>

#define NB   64
#define G    8
#define NT   512
#define TS   16
#define DIM  128
#define CLIP_LIM 256.0f

#define HROWS 8        // h rows per k3 block

__device__ float    g_cdf[NB * NT];           // [n][i][j][k]
__device__ float    g_P[DIM * NB * G * G];    // [d][n][j][k]
__device__ float    g_M[DIM * G];
__device__ unsigned g_minmax[2];

// ---------------------------------------------------------------- helpers
__device__ __forceinline__ float bspline5(float x) {
    float t = fabsf(x);
    float t2 = t * t, t3 = t2 * t, t4 = t2 * t2, t5 = t4 * t;
    if (t < 1.0f)
        return 11.0f/20.0f - 0.5f*t2 + 0.25f*t4 - t5*(1.0f/12.0f);
    if (t < 2.0f)
        return 17.0f/40.0f + t*(5.0f/8.0f) - t2*(7.0f/4.0f) + t3*(5.0f/4.0f)
             - t4*(3.0f/8.0f) + t5*(1.0f/24.0f);
    if (t < 3.0f) {
        float u = 3.0f - t;
        float u2 = u * u;
        return u2 * u2 * u * (1.0f/120.0f);
    }
    return 0.0f;
}

__device__ __forceinline__ int reflect_dct2(int i, int n) {
    int m = i % (2 * n);
    if (m < 0) m += 2 * n;
    return (m < n) ? m : (2 * n - 1 - m);
}

__device__ __forceinline__ unsigned fenc(float f) {
    unsigned u = __float_as_uint(f);
    return (u & 0x80000000u) ? ~u : (u | 0x80000000u);
}
__device__ __forceinline__ float fdec(unsigned e) {
    unsigned u = (e & 0x80000000u) ? (e & 0x7FFFFFFFu) : ~e;
    return __uint_as_float(u);
}

__device__ __forceinline__ float w1poly(float t) {
    return 17.0f/40.0f + t*(5.0f/8.0f + t*(-7.0f/4.0f + t*(5.0f/4.0f
         + t*(-3.0f/8.0f + t*(1.0f/24.0f)))));
}
__device__ __forceinline__ float w0poly(float t) {
    float t2 = t * t;
    float t4 = t2 * t2;
    return 11.0f/20.0f - 0.5f*t2 + 0.25f*t4 - t4*t*(1.0f/12.0f);
}

// ---------------------------------------------------------------- K0
__global__ void k0_matrix() {
    int s = threadIdx.x;
    if (s == 0) { g_minmax[0] = 0xFFFFFFFFu; g_minmax[1] = 0u; }
    if (s < DIM) {
        const float start = -0.53125f;
        const float step  = 8.0625f / 127.0f;
        float c = start + (float)s * step;
        float row[G];
        #pragma unroll
        for (int i = 0; i < G; i++) row[i] = 0.0f;
        int base = (int)floorf(c) - 2;
        #pragma unroll
        for (int t = 0; t < 6; t++) {
            int tap = base + t;
            float w = bspline5(c - (float)tap);
            row[reflect_dct2(tap, G)] += w;
        }
        #pragma unroll
        for (int i = 0; i < G; i++) g_M[s * G + i] = row[i];
    }
}

// ---------------------------------------------------------------- K1
__global__ void __launch_bounds__(256) k1_hist(const float* __restrict__ x) {
    __shared__ float hist8[8][NB];
    int tile = blockIdx.x;
    int ti = tile >> 6, tj = (tile >> 3) & 7, tk = tile & 7;
    int tid = threadIdx.x;
    int warp = tid >> 5;

    for (int i = tid; i < 8 * NB; i += 256) ((float*)hist8)[i] = 0.0f;
    __syncthreads();

    int d0 = ti * TS, h0 = tj * TS, w0 = tk * TS;
    const float4* x4 = (const float4*)x;

    #pragma unroll
    for (int it = 0; it < 4; it++) {
        int f  = it * 256 + tid;
        int w4 = f & 3;
        int rc = f >> 2;
        int a  = rc >> 4, b = rc & 15;
        float4 v = x4[((((d0 + a) * DIM) + (h0 + b)) * DIM + w0) / 4 + w4];

        float vv[4] = {v.x, v.y, v.z, v.w};
        #pragma unroll
        for (int q = 0; q < 4; q++) {
            float pos = vv[q] * 63.0f;
            int nb = __float2int_rn(pos);
            nb = min(63, max(0, nb));
            float u = (pos - (float)nb) * (1000.0f / 63.0f);
            float wgt = __expf(-0.5f * u * u);
            // weights < 1e-6 are numerically invisible after normalization
            if (wgt > 1e-6f) atomicAdd(&hist8[warp][nb], wgt);
        }
    }
    __syncthreads();

    if (tid < NB) {
        float s = 0.0f;
        #pragma unroll
        for (int w = 0; w < 8; w++) s += hist8[w][tid];
        hist8[0][tid] = s;
    }
    __syncthreads();

    if (tid == 0) {
        float s = 0.0f;
        float pdf[NB];
        for (int n = 0; n < NB; n++) { pdf[n] = hist8[0][n] * (1.0f / 4096.0f); s += pdf[n]; }
        float inv = 1.0f / (s + 1e-10f);
        float tot = 0.0f;
        float h2[NB];
        for (int n = 0; n < NB; n++) {
            float hh = fminf(pdf[n] * inv * 4096.0f, CLIP_LIM);
            h2[n] = hh;
            tot += hh;
        }
        float clipped  = 4096.0f - tot;
        float residual = fmodf(clipped, 64.0f);
        float redist   = (clipped - residual) * (1.0f / 64.0f);
        float c = 0.0f;
        int tbase = ti * 64 + tj * 8 + tk;
        for (int n = 0; n < NB; n++) {
            float hv = h2[n] + redist + (((float)n < residual) ? 1.0f : 0.0f);
            c += hv;
            g_cdf[n * NT + tbase] = c * (63.0f / 4096.0f);
        }
    }
}

// ---------------------------------------------------------------- K2
__global__ void k2_P() {
    int idx = blockIdx.x * blockDim.x + threadIdx.x;
    int k = idx & 7;
    int j = (idx >> 3) & 7;
    int n = (idx >> 6) & 63;
    int d = idx >> 12;
    float acc = 0.0f;
    #pragma unroll
    for (int i = 0; i < 8; i++)
        acc += g_M[d * 8 + i] * g_cdf[n * NT + i * 64 + j * 8 + k];
    g_P[idx] = acc;
}

// ---------------------------------------------------------------- K3
// grid (16, 128). R rows stored as fp16: one LDS.128 per tap (16 B), halving
// crossbar bytes vs fp32. Sync-free voxel loop, 4 voxels/thread.
__global__ void __launch_bounds__(256, 5) k3_final(const float* __restrict__ x,
                                                   float* __restrict__ out) {
    __shared__ __align__(16) __half sR[HROWS * NB * 8];   // 8192 B
    __shared__ float sMh[HROWS * G];                      // 256 B

    int d   = blockIdx.y;
    int hb  = blockIdx.x * HROWS;
    int tid = threadIdx.x;
    int hsub = tid >> 7;
    int w    = tid & 127;

    float xv[4];
    #pragma unroll
    for (int i = 0; i < 4; i++)
        xv[i] = x[(d * DIM + hb + 2 * i + hsub) * DIM + w];

    if (tid < HROWS * G) sMh[tid] = g_M[hb * G + tid];

    // P slice direct global->regs: P[d][bn][j][bq*2 .. bq*2+1]
    int bn = tid >> 2;          // 0..63
    int bq = tid & 3;           // 0..3
    float2 p[8];
    #pragma unroll
    for (int j = 0; j < 8; j++)
        p[j] = *(const float2*)&g_P[((d * NB + bn) * G + j) * G + bq * 2];

    float4 mwlo, mwhi;
    {
        const float* m = &g_M[w * G];
        mwlo = make_float4(m[0], m[1], m[2], m[3]);
        mwhi = make_float4(m[4], m[5], m[6], m[7]);
    }
    __syncthreads();   // sMh ready

    // build all 8 R rows in registers, store as half2 (conflict-free: warp
    // writes 32 consecutive half2 = 128 B)
    __half2* sR2 = (__half2*)sR;
    #pragma unroll
    for (int r = 0; r < HROWS; r++) {
        float2 a = make_float2(0.f, 0.f);
        #pragma unroll
        for (int j = 0; j < 8; j++) {
            float m = sMh[r * 8 + j];
            a.x = fmaf(m, p[j].x, a.x);
            a.y = fmaf(m, p[j].y, a.y);
        }
        sR2[r * NB * 4 + bn * 4 + bq] = __float22half2_rn(a);
    }
    __syncthreads();   // the ONLY barrier before the voxel loop

    float vmin =  3.0e38f, vmax = -3.0e38f;

    #pragma unroll
    for (int i = 0; i < 4; i++) {
        int r = 2 * i + hsub;
        float v  = xv[i];
        float cb = v * 63.0f;
        float fb = floorf(cb);
        int base = (int)fb - 2;
        float f  = cb - fb;
        float g1 = 1.0f - f;

        float f5g = f * f; f5g = f5g * f5g * f;
        float g5g = g1 * g1; g5g = g5g * g5g * g1;
        float wb[6];
        wb[0] = g5g * (1.0f / 120.0f);
        wb[1] = w1poly(1.0f + f);
        wb[2] = w0poly(f);
        wb[3] = w0poly(g1);
        wb[4] = w1poly(2.0f - f);
        wb[5] = f5g * (1.0f / 120.0f);

        const uint4* Rr = (const uint4*)(sR + r * NB * 8);
        float acc = 0.0f;
        #pragma unroll
        for (int t = 0; t < 6; t++) {
            int tap = base + t;
            int n = (tap < 0) ? (-1 - tap) : ((tap > 63) ? (127 - tap) : tap);
            uint4 u = Rr[n];                       // one LDS.128: 8 halves
            float2 f0 = __half22float2(*reinterpret_cast<__half2*>(&u.x));
            float2 f1 = __half22float2(*reinterpret_cast<__half2*>(&u.y));
            float2 f2 = __half22float2(*reinterpret_cast<__half2*>(&u.z));
            float2 f3 = __half22float2(*reinterpret_cast<__half2*>(&u.w));
            float s = mwlo.x * f0.x + mwlo.y * f0.y + mwlo.z * f1.x + mwlo.w * f1.y
                    + mwhi.x * f2.x + mwhi.y * f2.y + mwhi.z * f3.x + mwhi.w * f3.y;
            acc = fmaf(wb[t], s, acc);
        }
        out[(d * DIM + hb + r) * DIM + w] = acc;
        vmin = fminf(vmin, acc);
        vmax = fmaxf(vmax, acc);
    }

    #pragma unroll
    for (int off = 16; off > 0; off >>= 1) {
        vmin = fminf(vmin, __shfl_xor_sync(0xFFFFFFFFu, vmin, off));
        vmax = fmaxf(vmax, __shfl_xor_sync(0xFFFFFFFFu, vmax, off));
    }
    if ((tid & 31) == 0) {
        atomicMin(&g_minmax[0], fenc(vmin));
        atomicMax(&g_minmax[1], fenc(vmax));
    }
}

// ---------------------------------------------------------------- K4
__global__ void k4_norm(float4* __restrict__ out, int n4) {
    int i = blockIdx.x * blockDim.x + threadIdx.x;
    float mn = fdec(g_minmax[0]);
    float mx = fdec(g_minmax[1]);
    float inv = 1.0f / (mx - mn + 1e-10f);
    if (i < n4) {
        float4 v = out[i];
        v.x = (v.x - mn) * inv;
        v.y = (v.y - mn) * inv;
        v.z = (v.z - mn) * inv;
        v.w = (v.w - mn) * inv;
        out[i] = v;
    }
}

// ---------------------------------------------------------------- launch
extern "C" void kernel_launch(void* const* d_in, const int* in_sizes, int n_in,
                              void* d_out, int out_size) {
    const float* x = (const float*)d_in[0];
    float* out = (float*)d_out;

    k0_matrix<<<1, 128>>>();
    k1_hist<<<NT, 256>>>(x);
    k2_P<<<(DIM * NB * G * G) / 256, 256>>>();
    k3_final<<<dim3(DIM / HROWS, DIM), 256>>>(x, out);
    int n4 = out_size / 4;
    k4_norm<<<(n4 + 255) / 256, 256>>>((float4*)out, n4);
}

// round 7
// speedup vs baseline: 1.5034x; 1.0680x over previous
#include <cuda_runtime.h>
#include <cuda_fp16.h>
#include <math.h>

#define NB   64
#define G    8
#define NT   512
#define TS   16
#define DIM  128
#define CLIP_LIM 256.0f

#define HROWS 8        // h rows per k3 block
#define PROWS 68       // padded sR rows: tap+2 in [0,68)

__device__ float    g_cdf[NB * NT];           // [n][i][j][k]
__device__ float    g_P[DIM * NB * G * G];    // [d][n][j][k]
__device__ float    g_M[DIM * G];
__device__ unsigned g_minmax[2];

// ---------------------------------------------------------------- helpers
__device__ __forceinline__ float bspline5(float x) {
    float t = fabsf(x);
    float t2 = t * t, t3 = t2 * t, t4 = t2 * t2, t5 = t4 * t;
    if (t < 1.0f)
        return 11.0f/20.0f - 0.5f*t2 + 0.25f*t4 - t5*(1.0f/12.0f);
    if (t < 2.0f)
        return 17.0f/40.0f + t*(5.0f/8.0f) - t2*(7.0f/4.0f) + t3*(5.0f/4.0f)
             - t4*(3.0f/8.0f) + t5*(1.0f/24.0f);
    if (t < 3.0f) {
        float u = 3.0f - t;
        float u2 = u * u;
        return u2 * u2 * u * (1.0f/120.0f);
    }
    return 0.0f;
}

__device__ __forceinline__ int reflect_dct2(int i, int n) {
    int m = i % (2 * n);
    if (m < 0) m += 2 * n;
    return (m < n) ? m : (2 * n - 1 - m);
}

__device__ __forceinline__ unsigned fenc(float f) {
    unsigned u = __float_as_uint(f);
    return (u & 0x80000000u) ? ~u : (u | 0x80000000u);
}
__device__ __forceinline__ float fdec(unsigned e) {
    unsigned u = (e & 0x80000000u) ? (e & 0x7FFFFFFFu) : ~e;
    return __uint_as_float(u);
}

__device__ __forceinline__ float w1poly(float t) {
    return 17.0f/40.0f + t*(5.0f/8.0f + t*(-7.0f/4.0f + t*(5.0f/4.0f
         + t*(-3.0f/8.0f + t*(1.0f/24.0f)))));
}
__device__ __forceinline__ float w0poly(float t) {
    float t2 = t * t;
    float t4 = t2 * t2;
    return 11.0f/20.0f - 0.5f*t2 + 0.25f*t4 - t4*t*(1.0f/12.0f);
}

// ---------------------------------------------------------------- K1 (+ fused k0 matrix block)
__global__ void __launch_bounds__(256) k1_hist(const float* __restrict__ x) {
    int tid = threadIdx.x;

    // fused k0: last block computes the axis matrix instead of a histogram
    if (blockIdx.x == NT) {
        int s = tid;
        if (s < DIM) {
            const float start = -0.53125f;
            const float step  = 8.0625f / 127.0f;
            float c = start + (float)s * step;
            float row[G];
            #pragma unroll
            for (int i = 0; i < G; i++) row[i] = 0.0f;
            int base = (int)floorf(c) - 2;
            #pragma unroll
            for (int t = 0; t < 6; t++) {
                int tap = base + t;
                float w = bspline5(c - (float)tap);
                row[reflect_dct2(tap, G)] += w;
            }
            #pragma unroll
            for (int i = 0; i < G; i++) g_M[s * G + i] = row[i];
        }
        return;
    }

    __shared__ float hist8[8][NB];
    int tile = blockIdx.x;
    int ti = tile >> 6, tj = (tile >> 3) & 7, tk = tile & 7;
    int warp = tid >> 5;

    for (int i = tid; i < 8 * NB; i += 256) ((float*)hist8)[i] = 0.0f;
    __syncthreads();

    int d0 = ti * TS, h0 = tj * TS, w0 = tk * TS;
    const float4* x4 = (const float4*)x;

    #pragma unroll
    for (int it = 0; it < 4; it++) {
        int f  = it * 256 + tid;
        int w4 = f & 3;
        int rc = f >> 2;
        int a  = rc >> 4, b = rc & 15;
        float4 v = x4[((((d0 + a) * DIM) + (h0 + b)) * DIM + w0) / 4 + w4];

        float vv[4] = {v.x, v.y, v.z, v.w};
        #pragma unroll
        for (int q = 0; q < 4; q++) {
            float pos = vv[q] * 63.0f;
            int nb = __float2int_rn(pos);
            nb = min(63, max(0, nb));
            float diff = pos - (float)nb;
            // beyond 0.27 bins the Gaussian weight is <1e-4 (bin mass ~10):
            // skip MUFU + atomic entirely
            if (fabsf(diff) < 0.27f) {
                float u = diff * (1000.0f / 63.0f);
                atomicAdd(&hist8[warp][nb], __expf(-0.5f * u * u));
            }
        }
    }
    __syncthreads();

    if (tid < NB) {
        float s = 0.0f;
        #pragma unroll
        for (int w = 0; w < 8; w++) s += hist8[w][tid];
        hist8[0][tid] = s;
    }
    __syncthreads();

    if (tid == 0) {
        float s = 0.0f;
        float pdf[NB];
        for (int n = 0; n < NB; n++) { pdf[n] = hist8[0][n] * (1.0f / 4096.0f); s += pdf[n]; }
        float inv = 1.0f / (s + 1e-10f);
        float tot = 0.0f;
        float h2[NB];
        for (int n = 0; n < NB; n++) {
            float hh = fminf(pdf[n] * inv * 4096.0f, CLIP_LIM);
            h2[n] = hh;
            tot += hh;
        }
        float clipped  = 4096.0f - tot;
        float residual = fmodf(clipped, 64.0f);
        float redist   = (clipped - residual) * (1.0f / 64.0f);
        float c = 0.0f;
        int tbase = ti * 64 + tj * 8 + tk;
        for (int n = 0; n < NB; n++) {
            float hv = h2[n] + redist + (((float)n < residual) ? 1.0f : 0.0f);
            c += hv;
            g_cdf[n * NT + tbase] = c * (63.0f / 4096.0f);
        }
    }
}

// ---------------------------------------------------------------- K2 (+ minmax reset)
__global__ void k2_P() {
    int idx = blockIdx.x * blockDim.x + threadIdx.x;
    if (idx == 0) { g_minmax[0] = 0xFFFFFFFFu; g_minmax[1] = 0u; }
    int k = idx & 7;
    int j = (idx >> 3) & 7;
    int n = (idx >> 6) & 63;
    int d = idx >> 12;
    float acc = 0.0f;
    #pragma unroll
    for (int i = 0; i < 8; i++)
        acc += g_M[d * 8 + i] * g_cdf[n * NT + i * 64 + j * 8 + k];
    g_P[idx] = acc;
}

// ---------------------------------------------------------------- K3
// grid (16, 128). fp16 R rows PADDED for reflection (tap+2 indexes directly).
// Build reads m-rows with LDS.128. Sync-free voxel loop, 4 voxels/thread.
__global__ void __launch_bounds__(256, 6) k3_final(const float* __restrict__ x,
                                                   float* __restrict__ out) {
    __shared__ __align__(16) __half sR[HROWS * PROWS * 8];  // 8704 B
    __shared__ __align__(16) float sMh[HROWS * G];          // 256 B

    int d   = blockIdx.y;
    int hb  = blockIdx.x * HROWS;
    int tid = threadIdx.x;
    int hsub = tid >> 7;
    int w    = tid & 127;

    float xv[4];
    #pragma unroll
    for (int i = 0; i < 4; i++)
        xv[i] = x[(d * DIM + hb + 2 * i + hsub) * DIM + w];

    if (tid < HROWS * G) sMh[tid] = g_M[hb * G + tid];

    // P slice direct global->regs: P[d][bn][j][bq*2 .. bq*2+1]
    int bn = tid >> 2;          // 0..63
    int bq = tid & 3;           // 0..3
    float2 p[8];
    #pragma unroll
    for (int j = 0; j < 8; j++)
        p[j] = *(const float2*)&g_P[((d * NB + bn) * G + j) * G + bq * 2];

    float4 mwlo, mwhi;
    {
        const float* m = &g_M[w * G];
        mwlo = make_float4(m[0], m[1], m[2], m[3]);
        mwhi = make_float4(m[4], m[5], m[6], m[7]);
    }
    __syncthreads();   // sMh ready

    // build all 8 R rows; padded layout: row (bn+2), plus edge duplicates
    // padded[0]=R[1], padded[1]=R[0], padded[66]=R[63], padded[67]=R[62]
    __half2* sR2 = (__half2*)sR;
    #pragma unroll
    for (int r = 0; r < HROWS; r++) {
        float4 m01 = *(const float4*)&sMh[r * 8];
        float4 m23 = *(const float4*)&sMh[r * 8 + 4];
        float2 a = make_float2(0.f, 0.f);
        a.x = fmaf(m01.x, p[0].x, a.x);  a.y = fmaf(m01.x, p[0].y, a.y);
        a.x = fmaf(m01.y, p[1].x, a.x);  a.y = fmaf(m01.y, p[1].y, a.y);
        a.x = fmaf(m01.z, p[2].x, a.x);  a.y = fmaf(m01.z, p[2].y, a.y);
        a.x = fmaf(m01.w, p[3].x, a.x);  a.y = fmaf(m01.w, p[3].y, a.y);
        a.x = fmaf(m23.x, p[4].x, a.x);  a.y = fmaf(m23.x, p[4].y, a.y);
        a.x = fmaf(m23.y, p[5].x, a.x);  a.y = fmaf(m23.y, p[5].y, a.y);
        a.x = fmaf(m23.z, p[6].x, a.x);  a.y = fmaf(m23.z, p[6].y, a.y);
        a.x = fmaf(m23.w, p[7].x, a.x);  a.y = fmaf(m23.w, p[7].y, a.y);
        __half2 h = __float22half2_rn(a);
        int rb = r * PROWS * 4;
        sR2[rb + (bn + 2) * 4 + bq] = h;
        if (bn == 1)  sR2[rb + 0 * 4 + bq] = h;   // padded[0]  = R[1]
        if (bn == 0)  sR2[rb + 1 * 4 + bq] = h;   // padded[1]  = R[0]
        if (bn == 63) sR2[rb + 66 * 4 + bq] = h;  // padded[66] = R[63]
        if (bn == 62) sR2[rb + 67 * 4 + bq] = h;  // padded[67] = R[62]
    }
    __syncthreads();   // the ONLY barrier before the voxel loop

    float vmin =  3.0e38f, vmax = -3.0e38f;

    #pragma unroll
    for (int i = 0; i < 4; i++) {
        int r = 2 * i + hsub;
        float v  = xv[i];
        float cb = v * 63.0f;
        float fb = floorf(cb);
        int t2   = (int)fb;          // padded row of first tap: base+2 = floor(cb)
        float f  = cb - fb;
        float g1 = 1.0f - f;

        float f5g = f * f; f5g = f5g * f5g * f;
        float g5g = g1 * g1; g5g = g5g * g5g * g1;
        float wb[6];
        wb[0] = g5g * (1.0f / 120.0f);
        wb[1] = w1poly(1.0f + f);
        wb[2] = w0poly(f);
        wb[3] = w0poly(g1);
        wb[4] = w1poly(2.0f - f);
        wb[5] = f5g * (1.0f / 120.0f);

        const uint4* Rr = (const uint4*)(sR + r * PROWS * 8) + t2;
        float acc = 0.0f;
        #pragma unroll
        for (int t = 0; t < 6; t++) {
            uint4 u = Rr[t];                       // one LDS.128: 8 halves
            float2 f0 = __half22float2(*reinterpret_cast<__half2*>(&u.x));
            float2 f1 = __half22float2(*reinterpret_cast<__half2*>(&u.y));
            float2 f2 = __half22float2(*reinterpret_cast<__half2*>(&u.z));
            float2 f3 = __half22float2(*reinterpret_cast<__half2*>(&u.w));
            float s = mwlo.x * f0.x + mwlo.y * f0.y + mwlo.z * f1.x + mwlo.w * f1.y
                    + mwhi.x * f2.x + mwhi.y * f2.y + mwhi.z * f3.x + mwhi.w * f3.y;
            acc = fmaf(wb[t], s, acc);
        }
        out[(d * DIM + hb + r) * DIM + w] = acc;
        vmin = fminf(vmin, acc);
        vmax = fmaxf(vmax, acc);
    }

    #pragma unroll
    for (int off = 16; off > 0; off >>= 1) {
        vmin = fminf(vmin, __shfl_xor_sync(0xFFFFFFFFu, vmin, off));
        vmax = fmaxf(vmax, __shfl_xor_sync(0xFFFFFFFFu, vmax, off));
    }
    if ((tid & 31) == 0) {
        atomicMin(&g_minmax[0], fenc(vmin));
        atomicMax(&g_minmax[1], fenc(vmax));
    }
}

// ---------------------------------------------------------------- K4
__global__ void k4_norm(float4* __restrict__ out, int n4) {
    int i = blockIdx.x * blockDim.x + threadIdx.x;
    float mn = fdec(g_minmax[0]);
    float mx = fdec(g_minmax[1]);
    float inv = 1.0f / (mx - mn + 1e-10f);
    if (i < n4) {
        float4 v = out[i];
        v.x = (v.x - mn) * inv;
        v.y = (v.y - mn) * inv;
        v.z = (v.z - mn) * inv;
        v.w = (v.w - mn) * inv;
        out[i] = v;
    }
}

// ---------------------------------------------------------------- launch
extern "C" void kernel_launch(void* const* d_in, const int* in_sizes, int n_in,
                              void* d_out, int out_size) {
    const float* x = (const float*)d_in[0];
    float* out = (float*)d_out;

    k1_hist<<<NT + 1, 256>>>(x);                       // includes axis-matrix block
    k2_P<<<(DIM * NB * G * G) / 256, 256>>>();         // includes minmax reset
    k3_final<<<dim3(DIM / HROWS, DIM), 256>>>(x, out);
    int n4 = out_size / 4;
    k4_norm<<<(n4 + 255) / 256, 256>>>((float4*)out, n4);
}

// round 8
// speedup vs baseline: 1.6515x; 1.0985x over previous
#include <cuda_runtime.h>
#include <cuda_fp16.h>
#include <math.h>

#define NB   64
#define G    8
#define NT   512
#define TS   16
#define DIM  128
#define CLIP_LIM 256.0f

#define HROWS 16       // h rows per k3 block
#define PROWS 68       // padded sR rows: tap+2 in [0,68)

__device__ float    g_cdf[NB * NT];           // [n][i][j][k]
__device__ float    g_P[DIM * NB * G * G];    // [d][n][j][k]
__device__ float    g_M[DIM * G];
__device__ unsigned g_minmax[2];

// ---------------------------------------------------------------- helpers
__device__ __forceinline__ float bspline5(float x) {
    float t = fabsf(x);
    float t2 = t * t, t3 = t2 * t, t4 = t2 * t2, t5 = t4 * t;
    if (t < 1.0f)
        return 11.0f/20.0f - 0.5f*t2 + 0.25f*t4 - t5*(1.0f/12.0f);
    if (t < 2.0f)
        return 17.0f/40.0f + t*(5.0f/8.0f) - t2*(7.0f/4.0f) + t3*(5.0f/4.0f)
             - t4*(3.0f/8.0f) + t5*(1.0f/24.0f);
    if (t < 3.0f) {
        float u = 3.0f - t;
        float u2 = u * u;
        return u2 * u2 * u * (1.0f/120.0f);
    }
    return 0.0f;
}

__device__ __forceinline__ int reflect_dct2(int i, int n) {
    int m = i % (2 * n);
    if (m < 0) m += 2 * n;
    return (m < n) ? m : (2 * n - 1 - m);
}

__device__ __forceinline__ unsigned fenc(float f) {
    unsigned u = __float_as_uint(f);
    return (u & 0x80000000u) ? ~u : (u | 0x80000000u);
}
__device__ __forceinline__ float fdec(unsigned e) {
    unsigned u = (e & 0x80000000u) ? (e & 0x7FFFFFFFu) : ~e;
    return __uint_as_float(u);
}

__device__ __forceinline__ float w1poly(float t) {
    return 17.0f/40.0f + t*(5.0f/8.0f + t*(-7.0f/4.0f + t*(5.0f/4.0f
         + t*(-3.0f/8.0f + t*(1.0f/24.0f)))));
}
__device__ __forceinline__ float w0poly(float t) {
    float t2 = t * t;
    float t4 = t2 * t2;
    return 11.0f/20.0f - 0.5f*t2 + 0.25f*t4 - t4*t*(1.0f/12.0f);
}

// ---------------------------------------------------------------- K1 (+ fused k0 matrix block)
__global__ void __launch_bounds__(256) k1_hist(const float* __restrict__ x) {
    int tid = threadIdx.x;

    if (blockIdx.x == NT) {          // fused k0: axis matrix
        int s = tid;
        if (s < DIM) {
            const float start = -0.53125f;
            const float step  = 8.0625f / 127.0f;
            float c = start + (float)s * step;
            float row[G];
            #pragma unroll
            for (int i = 0; i < G; i++) row[i] = 0.0f;
            int base = (int)floorf(c) - 2;
            #pragma unroll
            for (int t = 0; t < 6; t++) {
                int tap = base + t;
                float w = bspline5(c - (float)tap);
                row[reflect_dct2(tap, G)] += w;
            }
            #pragma unroll
            for (int i = 0; i < G; i++) g_M[s * G + i] = row[i];
        }
        return;
    }

    __shared__ float hist8[8][NB];
    int tile = blockIdx.x;
    int ti = tile >> 6, tj = (tile >> 3) & 7, tk = tile & 7;
    int warp = tid >> 5;

    for (int i = tid; i < 8 * NB; i += 256) ((float*)hist8)[i] = 0.0f;
    __syncthreads();

    int d0 = ti * TS, h0 = tj * TS, w0 = tk * TS;
    const float4* x4 = (const float4*)x;

    #pragma unroll
    for (int it = 0; it < 4; it++) {
        int f  = it * 256 + tid;
        int w4 = f & 3;
        int rc = f >> 2;
        int a  = rc >> 4, b = rc & 15;
        float4 v = x4[((((d0 + a) * DIM) + (h0 + b)) * DIM + w0) / 4 + w4];

        float vv[4] = {v.x, v.y, v.z, v.w};
        #pragma unroll
        for (int q = 0; q < 4; q++) {
            float pos = vv[q] * 63.0f;
            int nb = __float2int_rn(pos);
            nb = min(63, max(0, nb));
            float diff = pos - (float)nb;
            if (fabsf(diff) < 0.27f) {
                float u = diff * (1000.0f / 63.0f);
                atomicAdd(&hist8[warp][nb], __expf(-0.5f * u * u));
            }
        }
    }
    __syncthreads();

    if (tid < NB) {
        float s = 0.0f;
        #pragma unroll
        for (int w = 0; w < 8; w++) s += hist8[w][tid];
        hist8[0][tid] = s;
    }
    __syncthreads();

    if (tid == 0) {
        float s = 0.0f;
        float pdf[NB];
        for (int n = 0; n < NB; n++) { pdf[n] = hist8[0][n] * (1.0f / 4096.0f); s += pdf[n]; }
        float inv = 1.0f / (s + 1e-10f);
        float tot = 0.0f;
        float h2[NB];
        for (int n = 0; n < NB; n++) {
            float hh = fminf(pdf[n] * inv * 4096.0f, CLIP_LIM);
            h2[n] = hh;
            tot += hh;
        }
        float clipped  = 4096.0f - tot;
        float residual = fmodf(clipped, 64.0f);
        float redist   = (clipped - residual) * (1.0f / 64.0f);
        float c = 0.0f;
        int tbase = ti * 64 + tj * 8 + tk;
        for (int n = 0; n < NB; n++) {
            float hv = h2[n] + redist + (((float)n < residual) ? 1.0f : 0.0f);
            c += hv;
            g_cdf[n * NT + tbase] = c * (63.0f / 4096.0f);
        }
    }
}

// ---------------------------------------------------------------- K2 (+ minmax reset)
__global__ void k2_P() {
    int idx = blockIdx.x * blockDim.x + threadIdx.x;
    if (idx == 0) { g_minmax[0] = 0xFFFFFFFFu; g_minmax[1] = 0u; }
    int k = idx & 7;
    int j = (idx >> 3) & 7;
    int n = (idx >> 6) & 63;
    int d = idx >> 12;
    float acc = 0.0f;
    #pragma unroll
    for (int i = 0; i < 8; i++)
        acc += g_M[d * 8 + i] * g_cdf[n * NT + i * 64 + j * 8 + k];
    g_P[idx] = acc;
}

// ---------------------------------------------------------------- K3
// grid (8, 128). 16 h-rows/block; fp16 padded R rows; HFMA2 dot product.
__global__ void __launch_bounds__(256, 5) k3_final(const float* __restrict__ x,
                                                   float* __restrict__ out) {
    __shared__ __align__(16) __half sR[HROWS * PROWS * 8];  // 17408 B
    __shared__ __align__(16) float sMh[HROWS * G];          // 512 B

    int d   = blockIdx.y;
    int hb  = blockIdx.x * HROWS;
    int tid = threadIdx.x;
    int hsub = tid >> 7;
    int w    = tid & 127;

    if (tid < HROWS * G) sMh[tid] = g_M[hb * G + tid];

    // P slice direct global->regs: P[d][bn][j][bq*2 .. bq*2+1]
    int bn = tid >> 2;          // 0..63
    int bq = tid & 3;           // 0..3
    float2 p[8];
    #pragma unroll
    for (int j = 0; j < 8; j++)
        p[j] = *(const float2*)&g_P[((d * NB + bn) * G + j) * G + bq * 2];

    // per-thread w weights as half2 (for HFMA2 dot)
    __half2 mh[4];
    {
        const float* m = &g_M[w * G];
        mh[0] = __float22half2_rn(make_float2(m[0], m[1]));
        mh[1] = __float22half2_rn(make_float2(m[2], m[3]));
        mh[2] = __float22half2_rn(make_float2(m[4], m[5]));
        mh[3] = __float22half2_rn(make_float2(m[6], m[7]));
    }
    __syncthreads();   // sMh ready

    // build all 16 R rows; padded layout: row (bn+2) + edge duplicates
    __half2* sR2 = (__half2*)sR;
    #pragma unroll
    for (int r = 0; r < HROWS; r++) {
        float4 m01 = *(const float4*)&sMh[r * 8];
        float4 m23 = *(const float4*)&sMh[r * 8 + 4];
        float2 a = make_float2(0.f, 0.f);
        a.x = fmaf(m01.x, p[0].x, a.x);  a.y = fmaf(m01.x, p[0].y, a.y);
        a.x = fmaf(m01.y, p[1].x, a.x);  a.y = fmaf(m01.y, p[1].y, a.y);
        a.x = fmaf(m01.z, p[2].x, a.x);  a.y = fmaf(m01.z, p[2].y, a.y);
        a.x = fmaf(m01.w, p[3].x, a.x);  a.y = fmaf(m01.w, p[3].y, a.y);
        a.x = fmaf(m23.x, p[4].x, a.x);  a.y = fmaf(m23.x, p[4].y, a.y);
        a.x = fmaf(m23.y, p[5].x, a.x);  a.y = fmaf(m23.y, p[5].y, a.y);
        a.x = fmaf(m23.z, p[6].x, a.x);  a.y = fmaf(m23.z, p[6].y, a.y);
        a.x = fmaf(m23.w, p[7].x, a.x);  a.y = fmaf(m23.w, p[7].y, a.y);
        __half2 h = __float22half2_rn(a);
        int rb = r * PROWS * 4;
        sR2[rb + (bn + 2) * 4 + bq] = h;
        if (bn == 1)  sR2[rb + 0 * 4 + bq] = h;
        if (bn == 0)  sR2[rb + 1 * 4 + bq] = h;
        if (bn == 63) sR2[rb + 66 * 4 + bq] = h;
        if (bn == 62) sR2[rb + 67 * 4 + bq] = h;
    }

    // voxel prefetch after build (p regs dead -> lower peak pressure)
    float xv[8];
    #pragma unroll
    for (int i = 0; i < 8; i++)
        xv[i] = x[(d * DIM + hb + 2 * i + hsub) * DIM + w];
    __syncthreads();   // the ONLY barrier before the voxel loop

    float vmin =  3.0e38f, vmax = -3.0e38f;

    #pragma unroll
    for (int i = 0; i < 8; i++) {
        int r = 2 * i + hsub;
        float v  = xv[i];
        float cb = v * 63.0f;
        float fb = floorf(cb);
        int t2   = (int)fb;          // padded row of first tap
        float f  = cb - fb;
        float g1 = 1.0f - f;

        float f5g = f * f; f5g = f5g * f5g * f;
        float g5g = g1 * g1; g5g = g5g * g5g * g1;
        float wb[6];
        wb[0] = g5g * (1.0f / 120.0f);
        wb[1] = w1poly(1.0f + f);
        wb[2] = w0poly(f);
        wb[3] = w0poly(g1);
        wb[4] = w1poly(2.0f - f);
        wb[5] = f5g * (1.0f / 120.0f);

        const uint4* Rr = (const uint4*)(sR + r * PROWS * 8) + t2;
        float acc = 0.0f;
        #pragma unroll
        for (int t = 0; t < 6; t++) {
            uint4 u = Rr[t];                       // one LDS.128: 8 halves
            __half2 h0 = *reinterpret_cast<__half2*>(&u.x);
            __half2 h1 = *reinterpret_cast<__half2*>(&u.y);
            __half2 h2 = *reinterpret_cast<__half2*>(&u.z);
            __half2 h3 = *reinterpret_cast<__half2*>(&u.w);
            __half2 a2 = __hmul2(mh[0], h0);
            a2 = __hfma2(mh[1], h1, a2);
            a2 = __hfma2(mh[2], h2, a2);
            a2 = __hfma2(mh[3], h3, a2);
            float2 fa = __half22float2(a2);
            acc = fmaf(wb[t], fa.x + fa.y, acc);
        }
        out[(d * DIM + hb + r) * DIM + w] = acc;
        vmin = fminf(vmin, acc);
        vmax = fmaxf(vmax, acc);
    }

    #pragma unroll
    for (int off = 16; off > 0; off >>= 1) {
        vmin = fminf(vmin, __shfl_xor_sync(0xFFFFFFFFu, vmin, off));
        vmax = fmaxf(vmax, __shfl_xor_sync(0xFFFFFFFFu, vmax, off));
    }
    if ((tid & 31) == 0) {
        atomicMin(&g_minmax[0], fenc(vmin));
        atomicMax(&g_minmax[1], fenc(vmax));
    }
}

// ---------------------------------------------------------------- K4: 2 float4/thread
__global__ void k4_norm(float4* __restrict__ out, int n4) {
    int base = blockIdx.x * 512 + threadIdx.x;
    float mn = fdec(g_minmax[0]);
    float mx = fdec(g_minmax[1]);
    float inv = 1.0f / (mx - mn + 1e-10f);
    #pragma unroll
    for (int q = 0; q < 2; q++) {
        int i = base + q * 256;
        if (i < n4) {
            float4 v = out[i];
            v.x = (v.x - mn) * inv;
            v.y = (v.y - mn) * inv;
            v.z = (v.z - mn) * inv;
            v.w = (v.w - mn) * inv;
            out[i] = v;
        }
    }
}

// ---------------------------------------------------------------- launch
extern "C" void kernel_launch(void* const* d_in, const int* in_sizes, int n_in,
                              void* d_out, int out_size) {
    const float* x = (const float*)d_in[0];
    float* out = (float*)d_out;

    k1_hist<<<NT + 1, 256>>>(x);
    k2_P<<<(DIM * NB * G * G) / 256, 256>>>();
    k3_final<<<dim3(DIM / HROWS, DIM), 256>>>(x, out);
    int n4 = out_size / 4;
    k4_norm<<<(n4 + 511) / 512, 256>>>((float4*)out, n4);
}

// round 11
// speedup vs baseline: 1.9861x; 1.2026x over previous
#include <cuda_runtime.h>
#include <cuda_fp16.h>
#include <math.h>

#define NB   64
#define G    8
#define NT   512
#define TS   16
#define DIM  128
#define CLIP_LIM 256.0f

#define HROWS 16       // h rows per k3 block
#define PROWS 68       // padded sR rows: tap+2 in [0,68)

__device__ float    g_cdf[NB * NT];           // [n][i][j][k]
__device__ float    g_P[DIM * NB * G * G];    // [d][n][j][k]
__device__ float    g_M[DIM * G];
__device__ unsigned g_minmax[2];

// ---------------------------------------------------------------- helpers
__device__ __forceinline__ float bspline5(float x) {
    float t = fabsf(x);
    float t2 = t * t, t3 = t2 * t, t4 = t2 * t2, t5 = t4 * t;
    if (t < 1.0f)
        return 11.0f/20.0f - 0.5f*t2 + 0.25f*t4 - t5*(1.0f/12.0f);
    if (t < 2.0f)
        return 17.0f/40.0f + t*(5.0f/8.0f) - t2*(7.0f/4.0f) + t3*(5.0f/4.0f)
             - t4*(3.0f/8.0f) + t5*(1.0f/24.0f);
    if (t < 3.0f) {
        float u = 3.0f - t;
        float u2 = u * u;
        return u2 * u2 * u * (1.0f/120.0f);
    }
    return 0.0f;
}

__device__ __forceinline__ int reflect_dct2(int i, int n) {
    int m = i % (2 * n);
    if (m < 0) m += 2 * n;
    return (m < n) ? m : (2 * n - 1 - m);
}

__device__ __forceinline__ unsigned fenc(float f) {
    unsigned u = __float_as_uint(f);
    return (u & 0x80000000u) ? ~u : (u | 0x80000000u);
}
__device__ __forceinline__ float fdec(unsigned e) {
    unsigned u = (e & 0x80000000u) ? (e & 0x7FFFFFFFu) : ~e;
    return __uint_as_float(u);
}

__device__ __forceinline__ float w1poly(float t) {
    return 17.0f/40.0f + t*(5.0f/8.0f + t*(-7.0f/4.0f + t*(5.0f/4.0f
         + t*(-3.0f/8.0f + t*(1.0f/24.0f)))));
}
__device__ __forceinline__ float w0poly(float t) {
    float t2 = t * t;
    float t4 = t2 * t2;
    return 11.0f/20.0f - 0.5f*t2 + 0.25f*t4 - t4*t*(1.0f/12.0f);
}

// ---------------------------------------------------------------- K1 (+ fused k0 matrix block)
__global__ void __launch_bounds__(256) k1_hist(const float* __restrict__ x) {
    int tid = threadIdx.x;

    if (blockIdx.x == NT) {          // fused k0: axis matrix
        int s = tid;
        if (s < DIM) {
            const float start = -0.53125f;
            const float step  = 8.0625f / 127.0f;
            float c = start + (float)s * step;
            float row[G];
            #pragma unroll
            for (int i = 0; i < G; i++) row[i] = 0.0f;
            int base = (int)floorf(c) - 2;
            #pragma unroll
            for (int t = 0; t < 6; t++) {
                int tap = base + t;
                float w = bspline5(c - (float)tap);
                row[reflect_dct2(tap, G)] += w;
            }
            #pragma unroll
            for (int i = 0; i < G; i++) g_M[s * G + i] = row[i];
        }
        return;
    }

    __shared__ float hist8[8][NB];
    int tile = blockIdx.x;
    int ti = tile >> 6, tj = (tile >> 3) & 7, tk = tile & 7;
    int warp = tid >> 5;

    for (int i = tid; i < 8 * NB; i += 256) ((float*)hist8)[i] = 0.0f;
    __syncthreads();

    int d0 = ti * TS, h0 = tj * TS, w0 = tk * TS;
    const float4* x4 = (const float4*)x;

    #pragma unroll
    for (int it = 0; it < 4; it++) {
        int f  = it * 256 + tid;
        int w4 = f & 3;
        int rc = f >> 2;
        int a  = rc >> 4, b = rc & 15;
        float4 v = x4[((((d0 + a) * DIM) + (h0 + b)) * DIM + w0) / 4 + w4];

        float vv[4] = {v.x, v.y, v.z, v.w};
        #pragma unroll
        for (int q = 0; q < 4; q++) {
            float pos = vv[q] * 63.0f;
            int nb = __float2int_rn(pos);
            nb = min(63, max(0, nb));
            float diff = pos - (float)nb;
            if (fabsf(diff) < 0.27f) {
                float u = diff * (1000.0f / 63.0f);
                atomicAdd(&hist8[warp][nb], __expf(-0.5f * u * u));
            }
        }
    }
    __syncthreads();

    // warp-parallel epilogue: lane l owns bins 2l, 2l+1
    if (tid < 32) {
        int l = tid;
        float a = 0.0f, b = 0.0f;
        #pragma unroll
        for (int w = 0; w < 8; w++) { a += hist8[w][2 * l]; b += hist8[w][2 * l + 1]; }

        // histos[n] = raw[n] / (sum(raw)/4096 + 1e-10)
        float S = a + b;
        #pragma unroll
        for (int off = 16; off > 0; off >>= 1) S += __shfl_xor_sync(0xFFFFFFFFu, S, off);
        float inv = 1.0f / (S * (1.0f / 4096.0f) + 1e-10f);
        float ha = fminf(a * inv, CLIP_LIM);
        float hb = fminf(b * inv, CLIP_LIM);

        float T = ha + hb;
        #pragma unroll
        for (int off = 16; off > 0; off >>= 1) T += __shfl_xor_sync(0xFFFFFFFFu, T, off);
        float clipped  = 4096.0f - T;
        float residual = fmodf(clipped, 64.0f);
        float redist   = (clipped - residual) * (1.0f / 64.0f);

        float hva = ha + redist + (((float)(2 * l)     < residual) ? 1.0f : 0.0f);
        float hvb = hb + redist + (((float)(2 * l + 1) < residual) ? 1.0f : 0.0f);

        // inclusive scan over pair sums
        float ps = hva + hvb;
        float scan = ps;
        #pragma unroll
        for (int off = 1; off < 32; off <<= 1) {
            float t = __shfl_up_sync(0xFFFFFFFFu, scan, off);
            if (l >= off) scan += t;
        }
        float excl = scan - ps;
        int tbase = ti * 64 + tj * 8 + tk;
        const float sc = 63.0f / 4096.0f;
        g_cdf[(2 * l)     * NT + tbase] = (excl + hva) * sc;
        g_cdf[(2 * l + 1) * NT + tbase] = (excl + hva + hvb) * sc;
    }
}

// ---------------------------------------------------------------- K2 (+ minmax reset)
__global__ void k2_P() {
    int idx = blockIdx.x * blockDim.x + threadIdx.x;
    if (idx == 0) { g_minmax[0] = 0xFFFFFFFFu; g_minmax[1] = 0u; }
    int k = idx & 7;
    int j = (idx >> 3) & 7;
    int n = (idx >> 6) & 63;
    int d = idx >> 12;
    float acc = 0.0f;
    #pragma unroll
    for (int i = 0; i < 8; i++)
        acc += g_M[d * 8 + i] * g_cdf[n * NT + i * 64 + j * 8 + k];
    g_P[idx] = acc;
}

// ---------------------------------------------------------------- K3
// grid (8, 128). 16 h-rows/block; fp16 padded R rows; HFMA2 dot; 6 CTAs/SM.
__global__ void __launch_bounds__(256, 6) k3_final(const float* __restrict__ x,
                                                   float* __restrict__ out) {
    __shared__ __align__(16) __half sR[HROWS * PROWS * 8];  // 17408 B
    __shared__ __align__(16) float sMh[HROWS * G];          // 512 B

    int d   = blockIdx.y;
    int hb  = blockIdx.x * HROWS;
    int tid = threadIdx.x;
    int hsub = tid >> 7;
    int w    = tid & 127;

    if (tid < HROWS * G) sMh[tid] = g_M[hb * G + tid];

    // P slice direct global->regs: P[d][bn][j][bq*2 .. bq*2+1]
    int bn = tid >> 2;          // 0..63
    int bq = tid & 3;           // 0..3
    float2 p[8];
    #pragma unroll
    for (int j = 0; j < 8; j++)
        p[j] = *(const float2*)&g_P[((d * NB + bn) * G + j) * G + bq * 2];

    // per-thread w weights as half2 (for HFMA2 dot)
    __half2 mh[4];
    {
        const float* m = &g_M[w * G];
        mh[0] = __float22half2_rn(make_float2(m[0], m[1]));
        mh[1] = __float22half2_rn(make_float2(m[2], m[3]));
        mh[2] = __float22half2_rn(make_float2(m[4], m[5]));
        mh[3] = __float22half2_rn(make_float2(m[6], m[7]));
    }
    __syncthreads();   // sMh ready

    // mirror duplicate slot (padded reflection): bn 1->0, 0->1, 62->67, 63->66
    bool hasdup = (bn < 2) | (bn >= 62);
    int dupoff  = ((bn < 2) ? (1 - bn) : (129 - bn)) * 4 + bq;

    // build all 16 R rows; one predicated mirror store
    __half2* sR2 = (__half2*)sR;
    #pragma unroll
    for (int r = 0; r < HROWS; r++) {
        float4 m01 = *(const float4*)&sMh[r * 8];
        float4 m23 = *(const float4*)&sMh[r * 8 + 4];
        float2 a = make_float2(0.f, 0.f);
        a.x = fmaf(m01.x, p[0].x, a.x);  a.y = fmaf(m01.x, p[0].y, a.y);
        a.x = fmaf(m01.y, p[1].x, a.x);  a.y = fmaf(m01.y, p[1].y, a.y);
        a.x = fmaf(m01.z, p[2].x, a.x);  a.y = fmaf(m01.z, p[2].y, a.y);
        a.x = fmaf(m01.w, p[3].x, a.x);  a.y = fmaf(m01.w, p[3].y, a.y);
        a.x = fmaf(m23.x, p[4].x, a.x);  a.y = fmaf(m23.x, p[4].y, a.y);
        a.x = fmaf(m23.y, p[5].x, a.x);  a.y = fmaf(m23.y, p[5].y, a.y);
        a.x = fmaf(m23.z, p[6].x, a.x);  a.y = fmaf(m23.z, p[6].y, a.y);
        a.x = fmaf(m23.w, p[7].x, a.x);  a.y = fmaf(m23.w, p[7].y, a.y);
        __half2 h = __float22half2_rn(a);
        int rb = r * PROWS * 4;
        sR2[rb + (bn + 2) * 4 + bq] = h;
        if (hasdup) sR2[rb + dupoff] = h;
    }
    __syncthreads();   // the ONLY barrier before the voxel loop

    float vmin =  3.0e38f, vmax = -3.0e38f;

    const float* xrow = x + (d * DIM + hb + hsub) * DIM + w;
    float vcur = xrow[0];

    #pragma unroll
    for (int i = 0; i < 8; i++) {
        int r = 2 * i + hsub;
        float vnext = 0.0f;
        if (i < 7) vnext = xrow[(2 * i + 2) * DIM];

        float cb = vcur * 63.0f;
        float fb = floorf(cb);
        int t2   = (int)fb;          // padded row of first tap
        float f  = cb - fb;
        float g1 = 1.0f - f;

        float f5g = f * f; f5g = f5g * f5g * f;
        float g5g = g1 * g1; g5g = g5g * g5g * g1;
        float wb[6];
        wb[0] = g5g * (1.0f / 120.0f);
        wb[1] = w1poly(1.0f + f);
        wb[2] = w0poly(f);
        wb[3] = w0poly(g1);
        wb[4] = w1poly(2.0f - f);
        wb[5] = f5g * (1.0f / 120.0f);

        const uint4* Rr = (const uint4*)(sR + r * PROWS * 8) + t2;
        float acc = 0.0f;
        #pragma unroll
        for (int t = 0; t < 6; t++) {
            uint4 u = Rr[t];                       // one LDS.128: 8 halves
            __half2 h0 = *reinterpret_cast<__half2*>(&u.x);
            __half2 h1 = *reinterpret_cast<__half2*>(&u.y);
            __half2 h2 = *reinterpret_cast<__half2*>(&u.z);
            __half2 h3 = *reinterpret_cast<__half2*>(&u.w);
            __half2 a2 = __hmul2(mh[0], h0);
            a2 = __hfma2(mh[1], h1, a2);
            a2 = __hfma2(mh[2], h2, a2);
            a2 = __hfma2(mh[3], h3, a2);
            float2 fa = __half22float2(a2);
            acc = fmaf(wb[t], fa.x + fa.y, acc);
        }
        out[(d * DIM + hb + r) * DIM + w] = acc;
        vmin = fminf(vmin, acc);
        vmax = fmaxf(vmax, acc);
        vcur = vnext;
    }

    #pragma unroll
    for (int off = 16; off > 0; off >>= 1) {
        vmin = fminf(vmin, __shfl_xor_sync(0xFFFFFFFFu, vmin, off));
        vmax = fmaxf(vmax, __shfl_xor_sync(0xFFFFFFFFu, vmax, off));
    }
    if ((tid & 31) == 0) {
        atomicMin(&g_minmax[0], fenc(vmin));
        atomicMax(&g_minmax[1], fenc(vmax));
    }
}

// ---------------------------------------------------------------- K4: 4 float4/thread, loads batched before stores
__global__ void k4_norm(float4* __restrict__ out, int n4) {
    int i0 = blockIdx.x * 1024 + threadIdx.x;
    float mn = fdec(g_minmax[0]);
    float mx = fdec(g_minmax[1]);
    float inv = 1.0f / (mx - mn + 1e-10f);
    float4 v[4];
    #pragma unroll
    for (int q = 0; q < 4; q++) v[q] = out[i0 + q * 256];
    #pragma unroll
    for (int q = 0; q < 4; q++) {
        float4 r;
        r.x = (v[q].x - mn) * inv;
        r.y = (v[q].y - mn) * inv;
        r.z = (v[q].z - mn) * inv;
        r.w = (v[q].w - mn) * inv;
        out[i0 + q * 256] = r;
    }
}

// ---------------------------------------------------------------- launch
extern "C" void kernel_launch(void* const* d_in, const int* in_sizes, int n_in,
                              void* d_out, int out_size) {
    const float* x = (const float*)d_in[0];
    float* out = (float*)d_out;

    k1_hist<<<NT + 1, 256>>>(x);
    k2_P<<<(DIM * NB * G * G) / 256, 256>>>();
    k3_final<<<dim3(DIM / HROWS, DIM), 256>>>(x, out);
    int n4 = out_size / 4;                 // 524288 = 512 blocks * 1024 exactly
    k4_norm<<<n4 / 1024, 256>>>((float4*)out, n4);
}